// round 5
// baseline (speedup 1.0000x reference)
#include <cuda_runtime.h>
#include <cuda_bf16.h>
#include <math.h>

// TemporalAttention: out[d,b] = sum_s softmax_s((enc[b,s,:]·We_w + We_b)*ut)[s] * enc[b,s,d]
// R3 register-pipelined inner loop + perfectly balanced persistent grid:
// grid = 4*SMs CTAs, NSPLIT = SMs/4 splits per batch -> exactly 4 work units per CTA.
// Fused last-CTA-done split merge. No online max (scores bounded, fp32 exp safe).

#define D_DIM     256
#define WARPS     8
#define THREADS   (WARPS * 32)
#define MAXB      64
#define MAXSPLIT  48

// Per-(b,split) partial: 256 acc values + l (+1 pad)
__device__ float        g_scratch[MAXB * MAXSPLIT * (D_DIM + 2)];
__device__ unsigned int g_cnt[MAXB];   // zero-init; reset by merger each launch

__global__ __launch_bounds__(THREADS, 4) void ta_fused(
    const float* __restrict__ enc,
    const float* __restrict__ Ww,
    const float* __restrict__ Wb,
    const float* __restrict__ ut,
    float* __restrict__ out,
    int S, int B, int nsplit)
{
    const int w    = threadIdx.x >> 5;
    const int lane = threadIdx.x & 31;
    const int t    = threadIdx.x;

    // Per-lane slice of We_w (lane k owns d = 8k..8k+7) — hoisted, unit-independent
    float wv[8];
#pragma unroll
    for (int j = 0; j < 8; j++) wv[j] = Ww[lane * 8 + j];
    const float be = Wb[0];
    const float u  = ut[0];

    const int nunits = B * nsplit;

    for (int unit = blockIdx.x; unit < nunits; unit += gridDim.x) {
        const int b     = unit / nsplit;
        const int split = unit - b * nsplit;

        const int s0   = (int)(((long long)split * S) / nsplit);
        const int s1   = (int)(((long long)(split + 1) * S) / nsplit);
        const int rows = s1 - s0;
        const float* base = enc + ((long long)b * S + s0) * D_DIM;

        float l = 0.0f;
        float acc[8];
#pragma unroll
        for (int j = 0; j < 8; j++) acc[j] = 0.0f;

#define LOADPAIR(v0, v1, v2, v3, ri)                                                              \
        {                                                                                         \
            const float4* _p0 = (const float4*)(base + (long long)(ri) * D_DIM) + lane * 2;          \
            const float4* _p1 = (const float4*)(base + (long long)((ri) + WARPS) * D_DIM) + lane * 2; \
            v0 = __ldcs(_p0); v1 = __ldcs(_p0 + 1);                                               \
            v2 = __ldcs(_p1); v3 = __ldcs(_p1 + 1);                                               \
        }

#define PROCESS(v0, v1, v2, v3)                                                                   \
        {                                                                                         \
            float xA[8] = {v0.x, v0.y, v0.z, v0.w, v1.x, v1.y, v1.z, v1.w};                       \
            float xB[8] = {v2.x, v2.y, v2.z, v2.w, v3.x, v3.y, v3.z, v3.w};                       \
            float dA = 0.f, dB = 0.f;                                                             \
            _Pragma("unroll")                                                                     \
            for (int j = 0; j < 8; j++) {                                                         \
                dA = fmaf(xA[j], wv[j], dA);                                                      \
                dB = fmaf(xB[j], wv[j], dB);                                                      \
            }                                                                                     \
            _Pragma("unroll")                                                                     \
            for (int o = 16; o > 0; o >>= 1) {                                                    \
                dA += __shfl_xor_sync(0xffffffffu, dA, o);                                        \
                dB += __shfl_xor_sync(0xffffffffu, dB, o);                                        \
            }                                                                                     \
            float pA = __expf((dA + be) * u);                                                     \
            float pB = __expf((dB + be) * u);                                                     \
            l += pA + pB;                                                                         \
            _Pragma("unroll")                                                                     \
            for (int j = 0; j < 8; j++)                                                           \
                acc[j] = fmaf(pA, xA[j], fmaf(pB, xB[j], acc[j]));                                \
        }

        int r = w;
        if (r + WARPS < rows) {
            float4 c0, c1, c2, c3;
            LOADPAIR(c0, c1, c2, c3, r);
            int rn = r + 2 * WARPS;
            while (rn + WARPS < rows) {
                float4 n0, n1, n2, n3;
                LOADPAIR(n0, n1, n2, n3, rn);   // prefetch next pair
                PROCESS(c0, c1, c2, c3);        // process current (loads in flight)
                c0 = n0; c1 = n1; c2 = n2; c3 = n3;
                rn += 2 * WARPS;
            }
            PROCESS(c0, c1, c2, c3);
            r = rn;
        }
        // tail: single rows
        for (; r < rows; r += WARPS) {
            const float4* p0 = (const float4*)(base + (long long)r * D_DIM) + lane * 2;
            float4 a0 = __ldcs(p0), a1 = __ldcs(p0 + 1);
            float x[8] = {a0.x, a0.y, a0.z, a0.w, a1.x, a1.y, a1.z, a1.w};
            float d = 0.f;
#pragma unroll
            for (int j = 0; j < 8; j++) d = fmaf(x[j], wv[j], d);
#pragma unroll
            for (int o = 16; o > 0; o >>= 1) d += __shfl_xor_sync(0xffffffffu, d, o);
            float p = __expf((d + be) * u);
            l += p;
#pragma unroll
            for (int j = 0; j < 8; j++) acc[j] = fmaf(p, x[j], acc[j]);
        }

        // ---- combine warps within the CTA (plain sums) ----
        __shared__ float s_acc[WARPS][D_DIM];
        __shared__ float s_l[WARPS];
        __syncthreads();   // reuse safety across units
#pragma unroll
        for (int j = 0; j < 8; j++) s_acc[w][lane * 8 + j] = acc[j];
        if (lane == 0) s_l[w] = l;
        __syncthreads();

        float a = 0.0f;
#pragma unroll
        for (int i = 0; i < WARPS; i++) a += s_acc[i][t];

        float* o = g_scratch + ((long long)(b * nsplit + split)) * (D_DIM + 2);
        o[t] = a;
        if (t == 0) {
            float L = 0.0f;
#pragma unroll
            for (int i = 0; i < WARPS; i++) L += s_l[i];
            o[D_DIM] = L;
        }

        // ---- fused split-merge: last CTA per batch sums all nsplit partials ----
        __threadfence();
        __syncthreads();
        __shared__ unsigned int s_last;
        if (t == 0) s_last = (atomicAdd(&g_cnt[b], 1u) == (unsigned)(nsplit - 1));
        __syncthreads();
        if (s_last) {
            const float* sc = g_scratch + (long long)b * nsplit * (D_DIM + 2);
            float Lg = 0.0f, ag = 0.0f;
            for (int i = 0; i < nsplit; i++) {
                Lg += sc[i * (D_DIM + 2) + D_DIM];
                ag += sc[i * (D_DIM + 2) + t];
            }
            out[t * B + b] = ag / Lg;   // out is [D, B]
            if (t == 0) g_cnt[b] = 0;   // reset for next graph replay
        }
    }
}

extern "C" void kernel_launch(void* const* d_in, const int* in_sizes, int n_in,
                              void* d_out, int out_size)
{
    const float* enc = (const float*)d_in[0];
    const float* Ww  = (const float*)d_in[1];
    const float* Wb  = (const float*)d_in[2];
    const float* ut  = (const float*)d_in[3];
    float* out = (float*)d_out;

    const int D = in_sizes[1];           // 256
    const int B = out_size / D;          // 64
    const int S = in_sizes[0] / (B * D); // 4096

    int sms = 148;
    cudaDeviceGetAttribute(&sms, cudaDevAttrMultiProcessorCount, 0);
    int nsplit = sms / 4;                // 38 on GB300 (152 SMs)
    if (nsplit > MAXSPLIT) nsplit = MAXSPLIT;
    if (nsplit < 1) nsplit = 1;
    int grid = sms * 4;                  // 4 CTAs/SM, 4 units per CTA

    ta_fused<<<grid, THREADS>>>(enc, Ww, Wb, ut, out, S, B, nsplit);
}

// round 6
// speedup vs baseline: 1.2629x; 1.2629x over previous
#include <cuda_runtime.h>
#include <cuda_bf16.h>
#include <math.h>

// TemporalAttention: out[d,b] = sum_s softmax_s((enc[b,s,:]·We_w + We_b)*ut)[s] * enc[b,s,d]
// R3 register-pipelined loop, NSPLIT=19 -> 1216 CTAs = 2 x (152 SMs * 4 slots):
// full slot occupancy with HW backfill, fine-grained tail.
// Fused last-CTA-done split merge. No online max (scores bounded, fp32 exp safe).

#define D_DIM    256
#define NSPLIT   19
#define WARPS    8
#define THREADS  (WARPS * 32)
#define MAXB     128
#define MAXSPLIT 32

// Per-(b,split) partial: 256 acc values + l (+1 pad)
__device__ float        g_scratch[MAXB * MAXSPLIT * (D_DIM + 2)];
__device__ unsigned int g_cnt[MAXB];   // zero-init; reset by merger each launch

__global__ __launch_bounds__(THREADS, 4) void ta_fused(
    const float* __restrict__ enc,
    const float* __restrict__ Ww,
    const float* __restrict__ Wb,
    const float* __restrict__ ut,
    float* __restrict__ out,
    int S, int B)
{
    const int split = blockIdx.x;
    const int b     = blockIdx.y;
    const int w     = threadIdx.x >> 5;
    const int lane  = threadIdx.x & 31;

    // Per-lane slice of We_w (lane k owns d = 8k..8k+7)
    float wv[8];
#pragma unroll
    for (int j = 0; j < 8; j++) wv[j] = Ww[lane * 8 + j];
    const float be = Wb[0];
    const float u  = ut[0];

    const int s0   = (int)(((long long)split * S) / NSPLIT);
    const int s1   = (int)(((long long)(split + 1) * S) / NSPLIT);
    const int rows = s1 - s0;

    const float* base = enc + ((long long)b * S + s0) * D_DIM;

    float l = 0.0f;
    float acc[8];
#pragma unroll
    for (int j = 0; j < 8; j++) acc[j] = 0.0f;

#define LOADPAIR(v0, v1, v2, v3, ri)                                            \
    {                                                                           \
        const float4* _p0 = (const float4*)(base + (long long)(ri) * D_DIM) + lane * 2;          \
        const float4* _p1 = (const float4*)(base + (long long)((ri) + WARPS) * D_DIM) + lane * 2; \
        v0 = __ldcs(_p0); v1 = __ldcs(_p0 + 1);                                 \
        v2 = __ldcs(_p1); v3 = __ldcs(_p1 + 1);                                 \
    }

#define PROCESS(v0, v1, v2, v3)                                                 \
    {                                                                           \
        float xA[8] = {v0.x, v0.y, v0.z, v0.w, v1.x, v1.y, v1.z, v1.w};         \
        float xB[8] = {v2.x, v2.y, v2.z, v2.w, v3.x, v3.y, v3.z, v3.w};         \
        float dA = 0.f, dB = 0.f;                                               \
        _Pragma("unroll")                                                       \
        for (int j = 0; j < 8; j++) {                                           \
            dA = fmaf(xA[j], wv[j], dA);                                        \
            dB = fmaf(xB[j], wv[j], dB);                                        \
        }                                                                       \
        _Pragma("unroll")                                                       \
        for (int o = 16; o > 0; o >>= 1) {                                      \
            dA += __shfl_xor_sync(0xffffffffu, dA, o);                          \
            dB += __shfl_xor_sync(0xffffffffu, dB, o);                          \
        }                                                                       \
        float pA = __expf((dA + be) * u);                                       \
        float pB = __expf((dB + be) * u);                                       \
        l += pA + pB;                                                           \
        _Pragma("unroll")                                                       \
        for (int j = 0; j < 8; j++)                                             \
            acc[j] = fmaf(pA, xA[j], fmaf(pB, xB[j], acc[j]));                  \
    }

    int r = w;
    if (r + WARPS < rows) {
        float4 c0, c1, c2, c3;
        LOADPAIR(c0, c1, c2, c3, r);
        int rn = r + 2 * WARPS;
        while (rn + WARPS < rows) {
            float4 n0, n1, n2, n3;
            LOADPAIR(n0, n1, n2, n3, rn);   // prefetch next pair
            PROCESS(c0, c1, c2, c3);        // process current (loads in flight)
            c0 = n0; c1 = n1; c2 = n2; c3 = n3;
            rn += 2 * WARPS;
        }
        PROCESS(c0, c1, c2, c3);
        r = rn;
    }
    // tail: single rows
    for (; r < rows; r += WARPS) {
        const float4* p0 = (const float4*)(base + (long long)r * D_DIM) + lane * 2;
        float4 a0 = __ldcs(p0), a1 = __ldcs(p0 + 1);
        float x[8] = {a0.x, a0.y, a0.z, a0.w, a1.x, a1.y, a1.z, a1.w};
        float d = 0.f;
#pragma unroll
        for (int j = 0; j < 8; j++) d = fmaf(x[j], wv[j], d);
#pragma unroll
        for (int o = 16; o > 0; o >>= 1) d += __shfl_xor_sync(0xffffffffu, d, o);
        float p = __expf((d + be) * u);
        l += p;
#pragma unroll
        for (int j = 0; j < 8; j++) acc[j] = fmaf(p, x[j], acc[j]);
    }

    // ---- combine warps within the CTA (plain sums, no rescale) ----
    __shared__ float s_acc[WARPS][D_DIM];
    __shared__ float s_l[WARPS];
#pragma unroll
    for (int j = 0; j < 8; j++) s_acc[w][lane * 8 + j] = acc[j];
    if (lane == 0) s_l[w] = l;
    __syncthreads();

    const int t = threadIdx.x;  // 0..255 == d index
    float a = 0.0f;
#pragma unroll
    for (int i = 0; i < WARPS; i++) a += s_acc[i][t];

    float* o = g_scratch + ((long long)(b * NSPLIT + split)) * (D_DIM + 2);
    o[t] = a;
    if (t == 0) {
        float L = 0.0f;
#pragma unroll
        for (int i = 0; i < WARPS; i++) L += s_l[i];
        o[D_DIM] = L;
    }

    // ---- fused split-merge: last CTA per batch sums all NSPLIT partials ----
    __threadfence();
    __syncthreads();
    __shared__ unsigned int s_last;
    if (t == 0) s_last = (atomicAdd(&g_cnt[b], 1u) == (unsigned)(NSPLIT - 1));
    __syncthreads();
    if (!s_last) return;

    const float* sc = g_scratch + (long long)b * NSPLIT * (D_DIM + 2);
    float Lg = 0.0f, ag = 0.0f;
#pragma unroll
    for (int i = 0; i < NSPLIT; i++) {
        Lg += sc[i * (D_DIM + 2) + D_DIM];
        ag += sc[i * (D_DIM + 2) + t];
    }
    out[t * B + b] = ag / Lg;   // out is [D, B]

    if (t == 0) g_cnt[b] = 0;   // reset for next graph replay
}

extern "C" void kernel_launch(void* const* d_in, const int* in_sizes, int n_in,
                              void* d_out, int out_size)
{
    const float* enc = (const float*)d_in[0];
    const float* Ww  = (const float*)d_in[1];
    const float* Wb  = (const float*)d_in[2];
    const float* ut  = (const float*)d_in[3];
    float* out = (float*)d_out;

    const int D = in_sizes[1];           // 256
    const int B = out_size / D;          // 64
    const int S = in_sizes[0] / (B * D); // 4096

    dim3 grid(NSPLIT, B);
    ta_fused<<<grid, THREADS>>>(enc, Ww, Wb, ut, out, S, B);
}